// round 5
// baseline (speedup 1.0000x reference)
#include <cuda_runtime.h>

static constexpr int FEAS = 4096;
static constexpr int K    = 64;
static constexpr int ROWS_PER_BLK = 8;   // warp-per-row, 256 threads, 512 blocks

// Persistent device state (zero-init at load; every replay restores it).
__device__ float g_colsum[K];
__device__ float g_diag;
__device__ float g_scalar;        // 0.5*(|colsum|^2 + |V|_F^2) + bias
__device__ int   g_cross_count;
__device__ int   g_done;
__device__ int   g_mv_count;

__global__ __launch_bounds__(256, 8)
void fm_fused_kernel(const float4* __restrict__ x,
                     const float4* __restrict__ w,
                     const float*  __restrict__ cross,
                     const float*  __restrict__ linear_b,
                     float* __restrict__ out,
                     int n_blocks) {
    const int tid  = threadIdx.x;
    const int lane = tid & 31;
    const int warp = tid >> 5;

    __shared__ float s_col[256];
    __shared__ int   s_last;

    // ---------------- cross phase: this block's 8 rows (2KB) ----------------
    {
        const int k  = tid & (K - 1);
        const int ty = tid >> 6;                       // 0..3
        const int f0 = blockIdx.x * ROWS_PER_BLK + ty; // rows f0 and f0+4
        float v0 = cross[f0 * K + k];
        float v1 = cross[(f0 + 4) * K + k];
        s_col[tid] = v0 + v1;

        float dg = v0 * v0 + v1 * v1;                  // diag partial
        #pragma unroll
        for (int o = 16; o > 0; o >>= 1) dg += __shfl_down_sync(0xffffffffu, dg, o);
        if (lane == 0) atomicAdd(&g_diag, dg);         // 8 atomics/block
        __syncthreads();

        if (tid < K) {
            float cs = s_col[tid] + s_col[tid + 64] + s_col[tid + 128] + s_col[tid + 192];
            atomicAdd(&g_colsum[tid], cs);             // 64 atomics/block
        }
        __threadfence();
        __syncthreads();

        if (tid == 0)
            s_last = (atomicAdd(&g_cross_count, 1) == n_blocks - 1) ? 1 : 0;
        __syncthreads();

        if (s_last) {                                  // elected finalizer block
            if (warp == 0) {
                float a = g_colsum[lane];
                float b = g_colsum[lane + 32];
                float t = a * a + b * b;
                #pragma unroll
                for (int o = 16; o > 0; o >>= 1) t += __shfl_down_sync(0xffffffffu, t, o);
                if (lane == 0)
                    g_scalar = 0.5f * (t + g_diag) + linear_b[0];
            }
            __syncthreads();                           // scalar read of colsum done
            if (tid < K) g_colsum[tid] = 0.f;          // reset for next replay
            if (tid == 0) {
                g_diag = 0.f;
                g_cross_count = 0;
                __threadfence();
                atomicExch(&g_done, 1);                // release
            }
        }
    }

    // ---------------- matvec: warp-per-row, 8 rows/block --------------------
    const int row = blockIdx.x * ROWS_PER_BLK + warp;
    const float4* xr = x + (size_t)row * (FEAS / 4);

    float acc0 = 0.f, acc1 = 0.f, acc2 = 0.f, acc3 = 0.f;
    #pragma unroll
    for (int j = 0; j < 32; j += 4) {                  // 8 batches of 4+4 loads
        float4 xv[4], wv[4];
        #pragma unroll
        for (int u = 0; u < 4; u++) xv[u] = __ldcs(&xr[lane + (j + u) * 32]);
        #pragma unroll
        for (int u = 0; u < 4; u++) wv[u] = __ldg(&w[lane + (j + u) * 32]);
        acc0 += xv[0].x*wv[0].x + xv[0].y*wv[0].y + xv[0].z*wv[0].z + xv[0].w*wv[0].w;
        acc1 += xv[1].x*wv[1].x + xv[1].y*wv[1].y + xv[1].z*wv[1].z + xv[1].w*wv[1].w;
        acc2 += xv[2].x*wv[2].x + xv[2].y*wv[2].y + xv[2].z*wv[2].z + xv[2].w*wv[2].w;
        acc3 += xv[3].x*wv[3].x + xv[3].y*wv[3].y + xv[3].z*wv[3].z + xv[3].w*wv[3].w;
    }
    float acc = (acc0 + acc1) + (acc2 + acc3);

    #pragma unroll
    for (int o = 16; o > 0; o >>= 1)
        acc += __shfl_down_sync(0xffffffffu, acc, o);

    if (lane == 0) {
        // scalar is released ~2-3us into the kernel; dots finish much later
        while (*(volatile int*)&g_done == 0) __nanosleep(64);
        __threadfence();                               // acquire
        float z = acc + g_scalar;
        out[row] = 1.f / (1.f + __expf(-z));
    }
    __syncthreads();
    if (tid == 0) {
        if (atomicAdd(&g_mv_count, 1) == n_blocks - 1) {
            g_done = 0;                                // reset for next replay
            g_mv_count = 0;
        }
    }
}

extern "C" void kernel_launch(void* const* d_in, const int* in_sizes, int n_in,
                              void* d_out, int out_size) {
    const float* x        = (const float*)d_in[0];  // (B, FEAS)
    const float* cross    = (const float*)d_in[1];  // (FEAS, 1, K)
    const float* linear_w = (const float*)d_in[2];  // (1, FEAS)
    const float* linear_b = (const float*)d_in[3];  // (1,)
    float* out = (float*)d_out;

    const int B = in_sizes[0] / FEAS;               // 4096
    const int n_blocks = B / ROWS_PER_BLK;          // 512 (all resident: <148*8)

    fm_fused_kernel<<<n_blocks, 256>>>(
        (const float4*)x, (const float4*)linear_w, cross, linear_b, out, n_blocks);
}

// round 7
// speedup vs baseline: 1.6650x; 1.6650x over previous
#include <cuda_runtime.h>

// R7 = R6 resubmitted: R6 failed with "system not yet initialized" in harness
// init (broker/driver transient), never executed. Theory untested; rerun.

static constexpr int FEAS = 4096;
static constexpr int K    = 64;
static constexpr int NCROSS_BLKS = 64;
static constexpr int ROWS_PER_BLK = 8;     // 256 threads; warp owns a col-slice
static constexpr int F4_PER_ROW  = FEAS / 4;        // 1024
static constexpr int F4_PER_WARP = F4_PER_ROW / 8;  // 128 float4 = 512 cols

// Persistent device state (zero-init at load; every replay restores it).
__device__ float g_colsum[K];
__device__ float g_diag;
__device__ float g_scalar;
__device__ int   g_cross_count;
__device__ int   g_done;
__device__ int   g_mv_count;

__global__ __launch_bounds__(256)
void fm_fused_kernel(const float4* __restrict__ x,
                     const float4* __restrict__ w,
                     const float*  __restrict__ cross,
                     const float*  __restrict__ linear_b,
                     float* __restrict__ out,
                     int n_mv_blocks) {
    const int tid  = threadIdx.x;
    const int lane = tid & 31;
    const int warp = tid >> 5;

    if (blockIdx.x < NCROSS_BLKS) {
        // ---------------- cross slice: 64 rows x 64 cols (R4 proven) --------
        __shared__ float s_col[256];
        __shared__ float s_diag[256];
        __shared__ int   s_last;

        const int k    = tid & (K - 1);
        const int ty   = tid >> 6;
        const int base = blockIdx.x * 64;

        float col = 0.f, diag = 0.f;
        #pragma unroll 4
        for (int f = base + ty; f < base + 64; f += 4) {
            float v = cross[f * K + k];
            col  += v;
            diag += v * v;
        }
        s_col[tid]  = col;
        s_diag[tid] = diag;
        __syncthreads();

        if (tid < K) {
            float cs = s_col[tid] + s_col[tid + 64] + s_col[tid + 128] + s_col[tid + 192];
            atomicAdd(&g_colsum[tid], cs);
        }
        if (warp == 0) {
            float d = 0.f;
            #pragma unroll
            for (int i = 0; i < 8; i++) d += s_diag[lane + i * 32];
            #pragma unroll
            for (int o = 16; o > 0; o >>= 1) d += __shfl_down_sync(0xffffffffu, d, o);
            if (lane == 0) atomicAdd(&g_diag, d);
        }
        __threadfence();
        __syncthreads();

        if (tid == 0)
            s_last = (atomicAdd(&g_cross_count, 1) == NCROSS_BLKS - 1) ? 1 : 0;
        __syncthreads();

        if (s_last) {
            if (warp == 0) {
                float a = g_colsum[lane];
                float b = g_colsum[lane + 32];
                float t = a * a + b * b;
                #pragma unroll
                for (int o = 16; o > 0; o >>= 1) t += __shfl_down_sync(0xffffffffu, t, o);
                if (lane == 0) {
                    g_scalar = 0.5f * (t + g_diag) + linear_b[0];
                    __threadfence();
                    atomicExch(&g_done, 1);
                }
            }
            __syncthreads();
            if (tid < K) g_colsum[tid] = 0.f;
            if (tid == 0) { g_diag = 0.f; g_cross_count = 0; }
        }
        return;
    }

    // ------------- matvec: warp = 512-col slice of ALL 8 rows ---------------
    __shared__ float s_part[8][8];     // [warp][row]

    const int row0  = (blockIdx.x - NCROSS_BLKS) * ROWS_PER_BLK;
    const int wbase = warp * F4_PER_WARP;          // this warp's column slice

    // w slice: loaded ONCE into registers (4 float4 per lane)
    float4 wv[4];
    #pragma unroll
    for (int u = 0; u < 4; u++)
        wv[u] = __ldg(&w[wbase + lane + u * 32]);

    float acc[ROWS_PER_BLK];
    #pragma unroll
    for (int r = 0; r < ROWS_PER_BLK; r++) {
        const float4* xr = x + (size_t)(row0 + r) * F4_PER_ROW + wbase;
        float4 xv[4];
        #pragma unroll
        for (int u = 0; u < 4; u++) xv[u] = xr[lane + u * 32];
        float a = 0.f;
        #pragma unroll
        for (int u = 0; u < 4; u++)
            a += xv[u].x * wv[u].x + xv[u].y * wv[u].y
               + xv[u].z * wv[u].z + xv[u].w * wv[u].w;
        acc[r] = a;
    }

    // per-warp reduce each row's partial, write to smem
    #pragma unroll
    for (int r = 0; r < ROWS_PER_BLK; r++) {
        float a = acc[r];
        #pragma unroll
        for (int o = 16; o > 0; o >>= 1)
            a += __shfl_down_sync(0xffffffffu, a, o);
        if (lane == 0) s_part[warp][r] = a;
    }
    __syncthreads();

    // fold across the 8 warps: threads 0..63, sub-groups of 8 per row
    if (tid < 64) {
        const int row = tid >> 3;                  // 0..7
        const int wi  = tid & 7;                   // warp index
        float v = s_part[wi][row];
        #pragma unroll
        for (int o = 4; o > 0; o >>= 1)
            v += __shfl_down_sync(0xffffffffu, v, o, 8);
        if (wi == 0) {
            while (*(volatile int*)&g_done == 0) __nanosleep(64);
            __threadfence();                       // acquire
            float z = v + g_scalar;
            out[row0 + row] = 1.f / (1.f + __expf(-z));
        }
    }
    __syncthreads();
    if (tid == 0) {
        if (atomicAdd(&g_mv_count, 1) == n_mv_blocks - 1) {
            g_done = 0;
            g_mv_count = 0;
        }
    }
}

extern "C" void kernel_launch(void* const* d_in, const int* in_sizes, int n_in,
                              void* d_out, int out_size) {
    const float* x        = (const float*)d_in[0];  // (B, FEAS)
    const float* cross    = (const float*)d_in[1];  // (FEAS, 1, K)
    const float* linear_w = (const float*)d_in[2];  // (1, FEAS)
    const float* linear_b = (const float*)d_in[3];  // (1,)
    float* out = (float*)d_out;

    const int B = in_sizes[0] / FEAS;               // 4096
    const int n_mv = B / ROWS_PER_BLK;              // 512

    fm_fused_kernel<<<NCROSS_BLKS + n_mv, 256>>>(
        (const float4*)x, (const float4*)linear_w, cross, linear_b, out, n_mv);
}